// round 13
// baseline (speedup 1.0000x reference)
#include <cuda_runtime.h>
#include <cuda_bf16.h>
#include <cstdint>

// DIN forward via mma.sync bf16 tensor cores (compute_103-safe; no tcgen05).
// Algebra: att_in@W1 = h@Wb + bias,  Wb = (Wa+Wc) + t.*Wd  (per-batch, K=64),
//          bias tvec[j] = b1[j] + sum_e t[e]*(Wb_blk-Wc)[e][j].
// din_kernel (1 CTA/batch, 3 CTAs/SM): A=h bf16 [208x64], B=Wb bf16 [256n x 64k],
// warp mainloop: A frags for 2 m-tiles in regs, one ldmatrix.x4 per (nt-pair,kk)
// feeds 4 MMAs; epilogue fuses relu(.+tvec)*w2 into logits; softmax; ui;
// prediction head fused into the CTA tail (mlp_w1 bf16-packed, L1-resident).

#define BATCH 4096
#define SEQ   200
#define EMB   64
#define HID   256
#define NT    256

#define ASTR       72            // bf16 elems per row (64 + 8 pad)
#define ROWB       144           // bytes per row
#define MTILES     13
#define AROWS      208

typedef unsigned long long ull;

// ---- smem layout (bytes) ----
#define OFF_A      0
#define A_BYTES    (AROWS * ROWB)            // 29952
#define OFF_B      A_BYTES                   // [256 n][72 k] bf16
#define B_BYTES    (256 * ROWB)              // 36864
#define OFF_MISC   (OFF_B + B_BYTES)         // 66816
#define MO_HIST    0                         // int[200]
#define MO_TVAL    800                       // float[64]
#define MO_TW      1056                      // float2[256] {tvec, w2}
#define MO_LOGIT   3104                      // float[208]
#define MO_LOGW    3936                      // float[200]
#define MO_RED     4736                      // float[32]
#define MO_UIP     4864                      // float[512]
#define MO_MLPIN   6912                      // float[128]
#define MISC_BYTES 7424
#define SMEM_BYTES (OFF_MISC + MISC_BYTES)   // 74240 -> 3 CTAs/SM

__device__ __nv_bfloat162 g_wacd[EMB * HID]; // {Wa+Wc, Wd}
__device__ __nv_bfloat16  g_diff[EMB * HID]; // Wb_blk - Wc
__device__ __nv_bfloat162 g_mw1p[64 * HID];  // {mlp_w1[2k][j], mlp_w1[2k+1][j]}

__device__ __forceinline__ uint32_t smem_to_u32(const void* p) {
    uint32_t a;
    asm("{ .reg .u64 t; cvta.to.shared.u64 t, %1; cvt.u32.u64 %0, t; }"
        : "=r"(a) : "l"(p));
    return a;
}
__device__ __forceinline__ ull pack4bf(float a, float b, float c, float d) {
    __nv_bfloat162 lo = __floats2bfloat162_rn(a, b);
    __nv_bfloat162 hi = __floats2bfloat162_rn(c, d);
    uint32_t l32 = *(uint32_t*)&lo, h32 = *(uint32_t*)&hi;
    ull r;
    asm("mov.b64 %0, {%1, %2};" : "=l"(r) : "r"(l32), "r"(h32));
    return r;
}

#define LDSM_X4(r0, r1, r2, r3, addr) \
    asm volatile("ldmatrix.sync.aligned.m8n8.x4.shared.b16 {%0,%1,%2,%3}, [%4];" \
                 : "=r"(r0), "=r"(r1), "=r"(r2), "=r"(r3) : "r"(addr))
#define MMA16816(c0, c1, c2, c3, a0, a1, a2, a3, b0, b1) \
    asm volatile("mma.sync.aligned.m16n8k16.row.col.f32.bf16.bf16.f32 " \
                 "{%0,%1,%2,%3}, {%4,%5,%6,%7}, {%8,%9}, {%0,%1,%2,%3};" \
                 : "+f"(c0), "+f"(c1), "+f"(c2), "+f"(c3) \
                 : "r"(a0), "r"(a1), "r"(a2), "r"(a3), "r"(b0), "r"(b1))

__device__ __forceinline__ float block_reduce_sum(float v, float* red, int tid) {
    #pragma unroll
    for (int o = 16; o; o >>= 1) v += __shfl_xor_sync(0xffffffffu, v, o);
    if ((tid & 31) == 0) red[tid >> 5] = v;
    __syncthreads();
    if (tid < 32) {
        float r = (tid < 8) ? red[tid] : 0.0f;
        #pragma unroll
        for (int o = 4; o; o >>= 1) r += __shfl_xor_sync(0xffffffffu, r, o);
        if (tid == 0) red[0] = r;
    }
    __syncthreads();
    float out = red[0];
    __syncthreads();
    return out;
}
__device__ __forceinline__ float block_reduce_max(float v, float* red, int tid) {
    #pragma unroll
    for (int o = 16; o; o >>= 1) v = fmaxf(v, __shfl_xor_sync(0xffffffffu, v, o));
    if ((tid & 31) == 0) red[tid >> 5] = v;
    __syncthreads();
    if (tid < 32) {
        float r = (tid < 8) ? red[tid] : -3.4e38f;
        #pragma unroll
        for (int o = 4; o; o >>= 1) r = fmaxf(r, __shfl_xor_sync(0xffffffffu, r, o));
        if (tid == 0) red[0] = r;
    }
    __syncthreads();
    float out = red[0];
    __syncthreads();
    return out;
}

// ---------------- prep: static bf16 weight packs ----------------
__global__ void prep_kernel(const float* __restrict__ w1,
                            const float* __restrict__ mw1) {
    const int j = threadIdx.x;   // 0..255
    const int e = blockIdx.x;    // 0..63
    float wa = w1[e * HID + j];
    float wb = w1[(64 + e) * HID + j];
    float wc = w1[(128 + e) * HID + j];
    float wd = w1[(192 + e) * HID + j];
    g_wacd[e * HID + j] = __floats2bfloat162_rn(wa + wc, wd);
    g_diff[e * HID + j] = __float2bfloat16(wb - wc);
    // mlp_w1 pack: k-pair e -> {mw1[2e][j], mw1[2e+1][j]}
    g_mw1p[e * HID + j] =
        __floats2bfloat162_rn(mw1[2 * e * HID + j], mw1[(2 * e + 1) * HID + j]);
}

// ---------------- main: per-batch attention + fused head ----------------
__global__ __launch_bounds__(NT, 3)
void din_kernel(const int*   __restrict__ user_hist,
                const int*   __restrict__ target_item,
                const float* __restrict__ user_emb,
                const float* __restrict__ item_emb,
                const float* __restrict__ attn_b1,
                const float* __restrict__ attn_w2,
                const float* __restrict__ mlp_b1,
                const float* __restrict__ mlp_w2,
                const float* __restrict__ mlp_b2,
                float* __restrict__ out)
{
    extern __shared__ char smc[];
    const uint32_t smem_base = smem_to_u32(smc);
    const int tid = threadIdx.x, b = blockIdx.x;
    const int wid = tid >> 5, lane = tid & 31;

    char* miscc   = smc + OFF_MISC;
    int*    shist = (int*)(miscc + MO_HIST);
    float*  tvalS = (float*)(miscc + MO_TVAL);
    float2* twS   = (float2*)(miscc + MO_TW);
    float* logitS = (float*)(miscc + MO_LOGIT);
    float* logwS  = (float*)(miscc + MO_LOGW);
    float* redS   = (float*)(miscc + MO_RED);
    float* uipS   = (float*)(miscc + MO_UIP);
    float* mlpinS = (float*)(miscc + MO_MLPIN);

    // ---- phase 0: hist + target embedding ----
    if (tid < SEQ) shist[tid] = user_hist[b * SEQ + tid];
    if (tid < EMB) {
        int tgt = target_item[b];
        tvalS[tid] = item_emb[(size_t)tgt * EMB + tid];
    }
    __syncthreads();

    // ---- phase 1a: A = h bf16 [208 x 64], rows 200..207 zeroed ----
    {
        const float4* ue4 = (const float4*)user_emb;
        for (int u = tid; u < SEQ * 16; u += NT) {
            int s = u >> 4, q = u & 15;
            float4 h4 = ue4[(size_t)shist[s] * 16 + q];
            *(ull*)(smc + OFF_A + s * ROWB + q * 8) = pack4bf(h4.x, h4.y, h4.z, h4.w);
        }
        #pragma unroll
        for (int i = tid; i < 8 * ROWB / 4; i += NT)
            *(uint32_t*)(smc + OFF_A + SEQ * ROWB + i * 4) = 0;
    }

    // ---- phase 1b: B = Wb bf16 [256 n][64 k] + tvec ----
    {
        const int j = tid;
        float tv_acc = attn_b1[j];
        __nv_bfloat16* Brow = (__nv_bfloat16*)(smc + OFF_B + j * ROWB);
        #pragma unroll 8
        for (int e = 0; e < EMB; e += 2) {
            __nv_bfloat162 p0 = g_wacd[e * HID + j];
            __nv_bfloat162 p1 = g_wacd[(e + 1) * HID + j];
            float t0 = tvalS[e], t1 = tvalS[e + 1];
            float v0 = __bfloat162float(p0.x) + t0 * __bfloat162float(p0.y);
            float v1 = __bfloat162float(p1.x) + t1 * __bfloat162float(p1.y);
            *(__nv_bfloat162*)(Brow + e) = __floats2bfloat162_rn(v0, v1);
            tv_acc += t0 * __bfloat162float(g_diff[e * HID + j])
                    + t1 * __bfloat162float(g_diff[(e + 1) * HID + j]);
        }
        twS[j] = make_float2(tv_acc, attn_w2[j]);
    }
    __syncthreads();

    // ---- phase 2: GEMM [208x64]@[64x256] + fused relu*w2 logit epilogue ----
    {
        const uint32_t aBase = smem_base + OFF_A
                             + (uint32_t)(lane & 15) * ROWB + (uint32_t)(lane >> 4) * 16;
        const uint32_t bBase = smem_base + OFF_B
                             + (uint32_t)(lane & 7) * ROWB + (uint32_t)((lane >> 3) & 1) * 16
                             + (uint32_t)(lane >> 4) * (8 * ROWB);
        const int mt0 = wid, mt1 = wid + 8;
        const bool two = (mt1 < MTILES);

        uint32_t a0[4][4], a1[4][4];
        #pragma unroll
        for (int kk = 0; kk < 4; ++kk)
            LDSM_X4(a0[kk][0], a0[kk][1], a0[kk][2], a0[kk][3],
                    aBase + (uint32_t)mt0 * (16 * ROWB) + (uint32_t)kk * 32);
        if (two) {
            #pragma unroll
            for (int kk = 0; kk < 4; ++kk)
                LDSM_X4(a1[kk][0], a1[kk][1], a1[kk][2], a1[kk][3],
                        aBase + (uint32_t)mt1 * (16 * ROWB) + (uint32_t)kk * 32);
        }

        float p0 = 0.f, p1 = 0.f, p2 = 0.f, p3 = 0.f;
        #pragma unroll 2
        for (int ntp = 0; ntp < 16; ++ntp) {
            float c[2][2][4];   // [nt-sub][tile][frag]
            #pragma unroll
            for (int q = 0; q < 2; ++q)
                #pragma unroll
                for (int t = 0; t < 2; ++t)
                    #pragma unroll
                    for (int f = 0; f < 4; ++f) c[q][t][f] = 0.f;

            #pragma unroll
            for (int kk = 0; kk < 4; ++kk) {
                uint32_t b0, b1, b2, b3;
                LDSM_X4(b0, b1, b2, b3,
                        bBase + (uint32_t)ntp * (16 * ROWB) + (uint32_t)kk * 32);
                MMA16816(c[0][0][0], c[0][0][1], c[0][0][2], c[0][0][3],
                         a0[kk][0], a0[kk][1], a0[kk][2], a0[kk][3], b0, b1);
                MMA16816(c[1][0][0], c[1][0][1], c[1][0][2], c[1][0][3],
                         a0[kk][0], a0[kk][1], a0[kk][2], a0[kk][3], b2, b3);
                if (two) {
                    MMA16816(c[0][1][0], c[0][1][1], c[0][1][2], c[0][1][3],
                             a1[kk][0], a1[kk][1], a1[kk][2], a1[kk][3], b0, b1);
                    MMA16816(c[1][1][0], c[1][1][1], c[1][1][2], c[1][1][3],
                             a1[kk][0], a1[kk][1], a1[kk][2], a1[kk][3], b2, b3);
                }
            }
            #pragma unroll
            for (int q = 0; q < 2; ++q) {
                int nt = ntp * 2 + q;
                float4 tw = *(const float4*)(twS + (nt * 8 + (lane & 3) * 2));
                p0 += fmaxf(c[q][0][0] + tw.x, 0.f) * tw.y
                    + fmaxf(c[q][0][1] + tw.z, 0.f) * tw.w;
                p1 += fmaxf(c[q][0][2] + tw.x, 0.f) * tw.y
                    + fmaxf(c[q][0][3] + tw.z, 0.f) * tw.w;
                if (two) {
                    p2 += fmaxf(c[q][1][0] + tw.x, 0.f) * tw.y
                        + fmaxf(c[q][1][1] + tw.z, 0.f) * tw.w;
                    p3 += fmaxf(c[q][1][2] + tw.x, 0.f) * tw.y
                        + fmaxf(c[q][1][3] + tw.z, 0.f) * tw.w;
                }
            }
        }
        p0 += __shfl_xor_sync(0xffffffffu, p0, 1);
        p0 += __shfl_xor_sync(0xffffffffu, p0, 2);
        p1 += __shfl_xor_sync(0xffffffffu, p1, 1);
        p1 += __shfl_xor_sync(0xffffffffu, p1, 2);
        p2 += __shfl_xor_sync(0xffffffffu, p2, 1);
        p2 += __shfl_xor_sync(0xffffffffu, p2, 2);
        p3 += __shfl_xor_sync(0xffffffffu, p3, 1);
        p3 += __shfl_xor_sync(0xffffffffu, p3, 2);
        if ((lane & 3) == 0) {
            int r = mt0 * 16 + (lane >> 2);
            logitS[r] = p0;
            logitS[r + 8] = p1;
            if (two) {
                int r2 = mt1 * 16 + (lane >> 2);
                logitS[r2] = p2;
                logitS[r2 + 8] = p3;
            }
        }
    }
    __syncthreads();

    // ---- phase 3: softmax over S ----
    {
        float l = -3.4e38f;
        if (tid < SEQ) l = logitS[tid];
        float mx = block_reduce_max(l, redS, tid);
        float ex = (tid < SEQ) ? __expf(l - mx) : 0.0f;
        float sm = block_reduce_sum(ex, redS, tid);
        if (tid < SEQ) logwS[tid] = ex / sm;
    }
    __syncthreads();

    // ---- phase 4: user_interest from bf16 A tile (vectorized) ----
    {
        int ep = lane;            // e-pair 0..31
        int part = tid >> 5;      // 8 parts x 25 s
        float ax = 0.f, ay = 0.f;
        int sA = part * 25;
        #pragma unroll 5
        for (int s = sA; s < sA + 25; ++s) {
            float w = logwS[s];
            __nv_bfloat162 hv = *(const __nv_bfloat162*)(smc + OFF_A + s * ROWB + ep * 4);
            float2 f = __bfloat1622float2(hv);
            ax += w * f.x;
            ay += w * f.y;
        }
        uipS[part * 64 + ep * 2]     = ax;
        uipS[part * 64 + ep * 2 + 1] = ay;
    }
    __syncthreads();
    if (tid < EMB) {
        float ui = 0.f;
        #pragma unroll
        for (int p = 0; p < 8; ++p) ui += uipS[p * 64 + tid];
        mlpinS[tid] = ui;
    } else if (tid < 2 * EMB) {
        mlpinS[tid] = tvalS[tid - EMB];
    }
    __syncthreads();

    // ---- phase 5: fused prediction head (mlp_w1 bf16-packed, L1-resident) ----
    {
        const int j = tid;
        float acc = mlp_b1[j];
        const __nv_bfloat162* mw = g_mw1p + j;
        #pragma unroll 8
        for (int k = 0; k < 64; ++k) {
            __nv_bfloat162 w = __ldg(&mw[k * HID]);
            float2 in = *(const float2*)(mlpinS + 2 * k);
            acc += in.x * __bfloat162float(w.x) + in.y * __bfloat162float(w.y);
        }
        float p = fmaxf(acc, 0.f) * mlp_w2[j];
        float s2 = block_reduce_sum(p, redS, tid);
        if (tid == 0)
            out[b] = 1.0f / (1.0f + __expf(-(s2 + mlp_b2[0])));
    }
}

extern "C" void kernel_launch(void* const* d_in, const int* in_sizes, int n_in,
                              void* d_out, int out_size) {
    const int*   user_hist   = (const int*)  d_in[0];
    const int*   target_item = (const int*)  d_in[1];
    const float* user_emb    = (const float*)d_in[2];
    const float* item_emb    = (const float*)d_in[3];
    const float* attn_w1     = (const float*)d_in[4];
    const float* attn_b1     = (const float*)d_in[5];
    const float* attn_w2     = (const float*)d_in[6];
    // d_in[7] = attn_b2 (constant shift inside softmax -> no effect)
    const float* mlp_w1      = (const float*)d_in[8];
    const float* mlp_b1      = (const float*)d_in[9];
    const float* mlp_w2      = (const float*)d_in[10];
    const float* mlp_b2      = (const float*)d_in[11];
    float* out = (float*)d_out;

    cudaFuncSetAttribute(din_kernel,
                         cudaFuncAttributeMaxDynamicSharedMemorySize, SMEM_BYTES);
    prep_kernel<<<EMB, 256>>>(attn_w1, mlp_w1);
    din_kernel<<<BATCH, NT, SMEM_BYTES>>>(
        user_hist, target_item, user_emb, item_emb, attn_b1, attn_w2,
        mlp_b1, mlp_w2, mlp_b2, out);
}